// round 1
// baseline (speedup 1.0000x reference)
#include <cuda_runtime.h>
#include <cuda_bf16.h>
#include <cstdint>

// Problem dims (fixed by reference)
#define BB 64
#define TT 512
#define DD 1024
#define LL 32

// Scratch (no allocations allowed -> __device__ globals)
__device__ float g_emis[BB * TT * LL];   // 4 MB
__device__ float g_nll[BB];

// ---------------------------------------------------------------------------
// Kernel 1: emissions GEMM  C[32768,32] = A[32768,1024] * W^T + bias
// BM=64 rows/block, BK=32, 128 threads, 4x4 thread tile.
// ---------------------------------------------------------------------------
#define BM 64
#define BK 32
#define AP 68   // padded As row (floats): 68*4=272B (16B aligned), reduces bank conflicts
#define WP 36   // padded Ws row: 144B (16B aligned)

__global__ void __launch_bounds__(128) emis_kernel(const float* __restrict__ A,
                                                   const float* __restrict__ W,
                                                   const float* __restrict__ bias) {
    __shared__ float As[BK][AP];   // transposed: As[k][m]
    __shared__ float Ws[BK][WP];   // transposed: Ws[k][l]

    const int t   = threadIdx.x;
    const int row0 = blockIdx.x * BM;
    const int tm  = t >> 3;   // 0..15 -> rows tm*4 .. tm*4+3
    const int tn  = t & 7;    // 0..7  -> cols tn*4 .. tn*4+3

    float acc[4][4];
#pragma unroll
    for (int i = 0; i < 4; ++i)
#pragma unroll
        for (int j = 0; j < 4; ++j) acc[i][j] = 0.0f;

    for (int k0 = 0; k0 < DD; k0 += BK) {
        // ---- load A tile [64 rows x 32 k] : 512 float4, 4 per thread ----
#pragma unroll
        for (int i = 0; i < 4; ++i) {
            int f4  = t + 128 * i;          // 0..511
            int m   = f4 >> 3;              // row within tile
            int kk4 = (f4 & 7) << 2;        // k offset (multiple of 4)
            float4 v = *(const float4*)(A + (size_t)(row0 + m) * DD + k0 + kk4);
            As[kk4 + 0][m] = v.x;
            As[kk4 + 1][m] = v.y;
            As[kk4 + 2][m] = v.z;
            As[kk4 + 3][m] = v.w;
        }
        // ---- load W tile [32 l x 32 k] : 256 float4, 2 per thread ----
#pragma unroll
        for (int i = 0; i < 2; ++i) {
            int f4  = t + 128 * i;          // 0..255
            int l   = f4 >> 3;
            int kk4 = (f4 & 7) << 2;
            float4 v = *(const float4*)(W + (size_t)l * DD + k0 + kk4);
            Ws[kk4 + 0][l] = v.x;
            Ws[kk4 + 1][l] = v.y;
            Ws[kk4 + 2][l] = v.z;
            Ws[kk4 + 3][l] = v.w;
        }
        __syncthreads();

#pragma unroll
        for (int kk = 0; kk < BK; ++kk) {
            float a[4], w[4];
            *(float4*)a = *(const float4*)&As[kk][tm * 4];
            *(float4*)w = *(const float4*)&Ws[kk][tn * 4];
#pragma unroll
            for (int i = 0; i < 4; ++i)
#pragma unroll
                for (int j = 0; j < 4; ++j)
                    acc[i][j] = fmaf(a[i], w[j], acc[i][j]);
        }
        __syncthreads();
    }

    // epilogue: add bias, store
    float4 bv = *(const float4*)&bias[tn * 4];
#pragma unroll
    for (int i = 0; i < 4; ++i) {
        int row = row0 + tm * 4 + i;
        float4 o;
        o.x = acc[i][0] + bv.x;
        o.y = acc[i][1] + bv.y;
        o.z = acc[i][2] + bv.z;
        o.w = acc[i][3] + bv.w;
        *(float4*)&g_emis[(size_t)row * LL + tn * 4] = o;
    }
}

// ---------------------------------------------------------------------------
// Kernel 2: CRF forward scan + gold-path numerator. One warp per sequence.
// Linear-space recurrence: alpha'_j = c + log(sum_i exp(alpha_i - c) * E_ij) + e_j
// with E = exp(trans) held per-lane (column j) in registers.
// Renormalizer c refreshed every 4 steps (drift bound << fp32 exp range).
// ---------------------------------------------------------------------------
__global__ void __launch_bounds__(32) crf_scan(const float* __restrict__ start_t,
                                               const float* __restrict__ end_t,
                                               const float* __restrict__ trans,
                                               const int* __restrict__ labels) {
    const int b = blockIdx.x;
    const int j = threadIdx.x;          // state index (lane)
    const unsigned FULL = 0xffffffffu;
    const float L2E = 1.4426950408889634f;

    // E column j in registers
    float Ecol[LL];
#pragma unroll
    for (int i = 0; i < LL; ++i) Ecol[i] = __expf(trans[i * LL + j]);

    const float* eb = g_emis + (size_t)b * TT * LL;
    const int* lb = labels + b * TT;

    float alpha = start_t[j] + eb[j];          // t = 0
    int prev = lb[0];
    float num = __shfl_sync(FULL, alpha, prev);  // start[tg0] + e0[tg0]

    float c = 0.0f;
    float e_next = eb[LL + j];                 // prefetch t=1

    for (int t = 1; t < TT; ++t) {
        float e_j = e_next;
        if (t + 1 < TT) e_next = eb[(t + 1) * LL + j];
        int lt = lb[t];

        // numerator (uniform across lanes)
        num += trans[prev * LL + lt] + __shfl_sync(FULL, e_j, lt);
        prev = lt;

        // periodic renormalization
        if (((t - 1) & 3) == 0) c = __shfl_sync(FULL, alpha, 0);

        float p = exp2f((alpha - c) * L2E);

        float s0 = 0.f, s1 = 0.f, s2 = 0.f, s3 = 0.f;
#pragma unroll
        for (int i = 0; i < LL; i += 4) {
            s0 = fmaf(__shfl_sync(FULL, p, i + 0), Ecol[i + 0], s0);
            s1 = fmaf(__shfl_sync(FULL, p, i + 1), Ecol[i + 1], s1);
            s2 = fmaf(__shfl_sync(FULL, p, i + 2), Ecol[i + 2], s2);
            s3 = fmaf(__shfl_sync(FULL, p, i + 3), Ecol[i + 3], s3);
        }
        float s = (s0 + s1) + (s2 + s3);
        alpha = c + __logf(s) + e_j;
    }
    num += end_t[prev];

    // den = logsumexp_j(alpha_j + end_j)
    float v = alpha + end_t[j];
    float m = v;
#pragma unroll
    for (int o = 16; o; o >>= 1) m = fmaxf(m, __shfl_xor_sync(FULL, m, o));
    float se = exp2f((v - m) * L2E);
#pragma unroll
    for (int o = 16; o; o >>= 1) se += __shfl_xor_sync(FULL, se, o);
    float den = m + __logf(se);

    if (j == 0) g_nll[b] = den - num;   // -(num - den)
}

// ---------------------------------------------------------------------------
// Kernel 3: mean over batch -> scalar
// ---------------------------------------------------------------------------
__global__ void __launch_bounds__(32) finalize(float* __restrict__ out) {
    const unsigned FULL = 0xffffffffu;
    int j = threadIdx.x;
    float v = g_nll[j] + g_nll[j + 32];
#pragma unroll
    for (int o = 16; o; o >>= 1) v += __shfl_xor_sync(FULL, v, o);
    if (j == 0) out[0] = v * (1.0f / (float)BB);
}

// ---------------------------------------------------------------------------
// launch
// inputs: 0=embeddings[B,T,D] f32, 1=W[L,D] f32, 2=b[L] f32, 3=start_trans[L],
//         4=end_trans[L], 5=trans[L,L], 6=labels[B,T] i32, 7=mask (all True -> ignored)
// ---------------------------------------------------------------------------
extern "C" void kernel_launch(void* const* d_in, const int* in_sizes, int n_in,
                              void* d_out, int out_size) {
    const float* emb    = (const float*)d_in[0];
    const float* W      = (const float*)d_in[1];
    const float* bias   = (const float*)d_in[2];
    const float* startt = (const float*)d_in[3];
    const float* endt   = (const float*)d_in[4];
    const float* trans  = (const float*)d_in[5];
    const int*   labels = (const int*)d_in[6];
    // d_in[7] = mask: setup_inputs fixes it to all-True; reference path with
    // mask==1 everywhere is what we implement.

    emis_kernel<<<(BB * TT) / BM, 128>>>(emb, W, bias);
    crf_scan<<<BB, 32>>>(startt, endt, trans, labels);
    finalize<<<1, 32>>>((float*)d_out);
}

// round 2
// speedup vs baseline: 1.2250x; 1.2250x over previous
#include <cuda_runtime.h>
#include <cuda_bf16.h>
#include <cstdint>

// Problem dims (fixed by reference)
#define BB 64
#define TT 512
#define DD 1024
#define LL 32

// Scratch (no allocations allowed -> __device__ globals)
__device__ float g_q[BB * TT * LL];   // 4 MB: exp(emissions)
__device__ float g_nll[BB];

// ---------------------------------------------------------------------------
// Kernel 1: emissions GEMM  E[32768,32] = A[32768,1024] @ W^T + bias,
// epilogue writes q = exp(E).
// BM=64, BK=32, 128 threads, 4x4 thread tile, f32x2 packed FMA,
// cp.async (4B, transposing) double buffering.
// ---------------------------------------------------------------------------
#define BM 64
#define BK 32
#define APAD 68   // As row stride (floats): 272B, 16B-aligned
#define WPAD 36   // Ws row stride (floats): 144B, 16B-aligned

__device__ __forceinline__ void cpa4(uint32_t s, const float* g) {
    asm volatile("cp.async.ca.shared.global [%0], [%1], 4;" :: "r"(s), "l"(g));
}
__device__ __forceinline__ void cp_commit() {
    asm volatile("cp.async.commit_group;" ::: "memory");
}
__device__ __forceinline__ void fma2(unsigned long long& d, unsigned long long a,
                                     unsigned long long b) {
    asm("fma.rn.f32x2 %0, %1, %2, %0;" : "+l"(d) : "l"(a), "l"(b));
}
__device__ __forceinline__ unsigned long long dup2(float a) {
    unsigned long long r;
    asm("mov.b64 %0, {%1, %1};" : "=l"(r) : "f"(a));
    return r;
}

__global__ void __launch_bounds__(128) emis_kernel(const float* __restrict__ A,
                                                   const float* __restrict__ W,
                                                   const float* __restrict__ bias) {
    __shared__ float As[2][BK][APAD];   // [k][m]
    __shared__ float Ws[2][BK][WPAD];   // [k][l]

    const int t    = threadIdx.x;
    const int row0 = blockIdx.x * BM;
    const int tm   = t >> 3;   // 0..15
    const int tn   = t & 7;    // 0..7

    const uint32_t sAs0 = (uint32_t)__cvta_generic_to_shared(&As[0][0][0]);
    const uint32_t sAs1 = (uint32_t)__cvta_generic_to_shared(&As[1][0][0]);
    const uint32_t sWs0 = (uint32_t)__cvta_generic_to_shared(&Ws[0][0][0]);
    const uint32_t sWs1 = (uint32_t)__cvta_generic_to_shared(&Ws[1][0][0]);

    // issue one tile's async loads (transposing: global [m][k] -> smem [k][m])
    auto load_tile = [&](int tile, int buf) {
        const int k0 = tile * BK;
        const uint32_t sA = buf ? sAs1 : sAs0;
        const uint32_t sW = buf ? sWs1 : sWs0;
#pragma unroll
        for (int i = 0; i < 16; ++i) {            // A: 64*32 elems / 128 thr
            int e = t + 128 * i;
            int k = e & 31, m = e >> 5;
            cpa4(sA + (uint32_t)(k * APAD + m) * 4,
                 A + (size_t)(row0 + m) * DD + k0 + k);
        }
#pragma unroll
        for (int i = 0; i < 8; ++i) {             // W: 32*32 elems / 128 thr
            int e = t + 128 * i;
            int k = e & 31, l = e >> 5;
            cpa4(sW + (uint32_t)(k * WPAD + l) * 4,
                 W + (size_t)l * DD + k0 + k);
        }
    };

    unsigned long long acc[4][2];
#pragma unroll
    for (int i = 0; i < 4; ++i) { acc[i][0] = 0ull; acc[i][1] = 0ull; }

    load_tile(0, 0); cp_commit();
    load_tile(1, 1); cp_commit();

    for (int it = 0; it < DD / BK; ++it) {
        if (it < DD / BK - 1)
            asm volatile("cp.async.wait_group 1;" ::: "memory");
        else
            asm volatile("cp.async.wait_group 0;" ::: "memory");
        __syncthreads();

        const int buf = it & 1;
#pragma unroll
        for (int kk = 0; kk < BK; ++kk) {
            float4 av = *(const float4*)&As[buf][kk][tm * 4];
            ulonglong2 wv = *(const ulonglong2*)&Ws[buf][kk][tn * 4];
            unsigned long long a0 = dup2(av.x), a1 = dup2(av.y),
                               a2 = dup2(av.z), a3 = dup2(av.w);
            fma2(acc[0][0], a0, wv.x); fma2(acc[0][1], a0, wv.y);
            fma2(acc[1][0], a1, wv.x); fma2(acc[1][1], a1, wv.y);
            fma2(acc[2][0], a2, wv.x); fma2(acc[2][1], a2, wv.y);
            fma2(acc[3][0], a3, wv.x); fma2(acc[3][1], a3, wv.y);
        }
        __syncthreads();

        if (it + 2 < DD / BK) { load_tile(it + 2, buf); cp_commit(); }
    }

    // epilogue: add bias, exp, store q
    float4 bv = *(const float4*)&bias[tn * 4];
#pragma unroll
    for (int i = 0; i < 4; ++i) {
        int row = row0 + tm * 4 + i;
        float c0 = __uint_as_float((unsigned)(acc[i][0] & 0xffffffffull));
        float c1 = __uint_as_float((unsigned)(acc[i][0] >> 32));
        float c2 = __uint_as_float((unsigned)(acc[i][1] & 0xffffffffull));
        float c3 = __uint_as_float((unsigned)(acc[i][1] >> 32));
        float4 o;
        o.x = __expf(c0 + bv.x);
        o.y = __expf(c1 + bv.y);
        o.z = __expf(c2 + bv.z);
        o.w = __expf(c3 + bv.w);
        *(float4*)&g_q[(size_t)row * LL + tn * 4] = o;
    }
}

// ---------------------------------------------------------------------------
// Kernel 2: CRF forward scan + gold-path numerator, one sequence per block.
// All of the sequence's q = exp(e) staged in shared by 128 threads; warp 0
// then runs a pure linear-space recurrence with per-step renormalization:
//   p'_j = (sum_i p_i * E_ij) * q_j * rinv ,  rinv = rcp(p_0),  logC += log(p_0)
// No MUFU on the critical chain (rcp/log run in parallel with the FMA chain).
// ---------------------------------------------------------------------------
#define SCAN_SMEM_FLOATS (TT * LL + LL * LL + TT)  // Qs + Ts + labels
#define SCAN_SMEM_BYTES  (SCAN_SMEM_FLOATS * 4)

__global__ void __launch_bounds__(128) crf_scan(const float* __restrict__ start_t,
                                                const float* __restrict__ end_t,
                                                const float* __restrict__ trans,
                                                const int* __restrict__ labels) {
    extern __shared__ float sm[];
    float* Qs = sm;                       // [TT][LL] = exp(emissions)
    float* Ts = sm + TT * LL;             // [LL][LL] raw trans
    int*   Ls = (int*)(sm + TT * LL + LL * LL);   // [TT] labels

    const int b = blockIdx.x;
    const int t = threadIdx.x;
    const unsigned FULL = 0xffffffffu;

    // cooperative stage-in (L2-resident after GEMM)
    {
        const float4* src = (const float4*)(g_q + (size_t)b * TT * LL);
        float4* dst = (float4*)Qs;
#pragma unroll
        for (int i = 0; i < (TT * LL) / (128 * 4); ++i)
            dst[t + 128 * i] = src[t + 128 * i];
        ((float4*)Ts)[t]       = ((const float4*)trans)[t];
        ((float4*)Ts)[t + 128] = ((const float4*)trans)[t + 128];
        ((int4*)Ls)[t] = ((const int4*)(labels + b * TT))[t];
    }
    __syncthreads();

    if (t >= 32) return;
    const int j = t;   // state index

    float Ecol[LL];
#pragma unroll
    for (int i = 0; i < LL; ++i) Ecol[i] = __expf(Ts[i * LL + j]);
    const float Eend = __expf(end_t[j]);

    float p = __expf(start_t[j]) * Qs[j];     // t = 0
    int prev = Ls[0];
    float num = start_t[prev] + __logf(Qs[prev]);
    float logC = 0.0f;

    float qn = Qs[LL + j];   // prefetch t=1

#pragma unroll 4
    for (int tt = 1; tt < TT; ++tt) {
        float q = qn;
        int tnext = (tt + 1 < TT) ? (tt + 1) : tt;
        qn = Qs[tnext * LL + j];

        int lt = Ls[tt];
        num += Ts[prev * LL + lt] + __logf(Qs[tt * LL + lt]);
        prev = lt;

        // matvec + renorm (renorm scalar path runs parallel to the fma chain)
        float s0 = 0.f, s1 = 0.f, s2 = 0.f, s3 = 0.f,
              s4 = 0.f, s5 = 0.f, s6 = 0.f, s7 = 0.f;
        float r0 = __shfl_sync(FULL, p, 0);
        s0 = fmaf(r0, Ecol[0], s0);
#pragma unroll
        for (int i = 1; i < LL; ++i) {
            float pi = __shfl_sync(FULL, p, i);
            switch (i & 7) {
                case 0: s0 = fmaf(pi, Ecol[i], s0); break;
                case 1: s1 = fmaf(pi, Ecol[i], s1); break;
                case 2: s2 = fmaf(pi, Ecol[i], s2); break;
                case 3: s3 = fmaf(pi, Ecol[i], s3); break;
                case 4: s4 = fmaf(pi, Ecol[i], s4); break;
                case 5: s5 = fmaf(pi, Ecol[i], s5); break;
                case 6: s6 = fmaf(pi, Ecol[i], s6); break;
                default: s7 = fmaf(pi, Ecol[i], s7); break;
            }
        }
        float rinv;
        asm("rcp.approx.f32 %0, %1;" : "=f"(rinv) : "f"(r0));
        logC += __logf(r0);
        float qr = q * rinv;
        float s = ((s0 + s1) + (s2 + s3)) + ((s4 + s5) + (s6 + s7));
        p = s * qr;
    }
    num += end_t[prev];

    // den = logC + log(sum_j p_j * exp(end_j))
    float v = p * Eend;
#pragma unroll
    for (int o = 16; o; o >>= 1) v += __shfl_xor_sync(FULL, v, o);
    float den = logC + __logf(v);

    if (j == 0) g_nll[b] = den - num;   // -(num - den)
}

// ---------------------------------------------------------------------------
// Kernel 3: mean over batch -> scalar
// ---------------------------------------------------------------------------
__global__ void __launch_bounds__(32) finalize(float* __restrict__ out) {
    const unsigned FULL = 0xffffffffu;
    int j = threadIdx.x;
    float v = g_nll[j] + g_nll[j + 32];
#pragma unroll
    for (int o = 16; o; o >>= 1) v += __shfl_xor_sync(FULL, v, o);
    if (j == 0) out[0] = v * (1.0f / (float)BB);
}

// ---------------------------------------------------------------------------
// launch
// inputs: 0=embeddings[B,T,D] f32, 1=W[L,D] f32, 2=b[L] f32, 3=start_trans[L],
//         4=end_trans[L], 5=trans[L,L], 6=labels[B,T] i32, 7=mask (all True)
// ---------------------------------------------------------------------------
extern "C" void kernel_launch(void* const* d_in, const int* in_sizes, int n_in,
                              void* d_out, int out_size) {
    const float* emb    = (const float*)d_in[0];
    const float* W      = (const float*)d_in[1];
    const float* bias   = (const float*)d_in[2];
    const float* startt = (const float*)d_in[3];
    const float* endt   = (const float*)d_in[4];
    const float* trans  = (const float*)d_in[5];
    const int*   labels = (const int*)d_in[6];

    static int smem_set = 0;
    if (!smem_set) {
        cudaFuncSetAttribute(crf_scan, cudaFuncAttributeMaxDynamicSharedMemorySize,
                             SCAN_SMEM_BYTES);
        smem_set = 1;
    }

    emis_kernel<<<(BB * TT) / BM, 128>>>(emb, W, bias);
    crf_scan<<<BB, 128, SCAN_SMEM_BYTES>>>(startt, endt, trans, labels);
    finalize<<<1, 32>>>((float*)d_out);
}

// round 3
// speedup vs baseline: 2.2693x; 1.8525x over previous
#include <cuda_runtime.h>
#include <cuda_bf16.h>
#include <cstdint>

#define BB 64
#define TT 512
#define DD 1024
#define LL 32

__device__ float g_q[BB * TT * LL];   // 4 MB: exp(emissions)
__device__ float g_nll[BB];

// ---------------------------------------------------------------------------
// packed f32x2 helpers
// ---------------------------------------------------------------------------
__device__ __forceinline__ void fma2(unsigned long long& d, unsigned long long a,
                                     unsigned long long b) {
    asm("fma.rn.f32x2 %0, %1, %2, %0;" : "+l"(d) : "l"(a), "l"(b));
}
__device__ __forceinline__ unsigned long long add2(unsigned long long a,
                                                   unsigned long long b) {
    unsigned long long r;
    asm("add.rn.f32x2 %0, %1, %2;" : "=l"(r) : "l"(a), "l"(b));
    return r;
}
__device__ __forceinline__ unsigned long long dup2(float a) {
    unsigned long long r;
    asm("mov.b64 %0, {%1, %1};" : "=l"(r) : "f"(a));
    return r;
}
__device__ __forceinline__ unsigned long long pack2(float lo, float hi) {
    unsigned long long r;
    asm("mov.b64 %0, {%1, %2};" : "=l"(r) : "f"(lo), "f"(hi));
    return r;
}
__device__ __forceinline__ float2 unpack2(unsigned long long v) {
    float2 f;
    asm("mov.b64 {%0, %1}, %2;" : "=f"(f.x), "=f"(f.y) : "l"(v));
    return f;
}

// ---------------------------------------------------------------------------
// Kernel 1: emissions GEMM  q = exp(A @ W^T + bias)
// BM=64, BK=32, 128 threads, 4x4 thread tile, FFMA2, reg-staged LDG
// double buffering (no cp.async -> much lower LSU issue pressure).
// ---------------------------------------------------------------------------
#define BM 64
#define BK 32
#define APAD 68
#define WPAD 36

__global__ void __launch_bounds__(128, 5) emis_kernel(const float* __restrict__ A,
                                                      const float* __restrict__ W,
                                                      const float* __restrict__ bias) {
    __shared__ __align__(16) float As[2][BK][APAD];   // [k][m]
    __shared__ __align__(16) float Ws[2][BK][WPAD];   // [k][l]

    const int t    = threadIdx.x;
    const int row0 = blockIdx.x * BM;
    const int tm   = t >> 3;   // 0..15
    const int tn   = t & 7;    // 0..7

    float4 aR[4];
    float4 wR[2];

    auto ldg_tile = [&](int k0) {
#pragma unroll
        for (int i = 0; i < 4; ++i) {
            int f4 = t + 128 * i;
            int m = f4 >> 3, k4 = (f4 & 7) << 2;
            aR[i] = *(const float4*)(A + (size_t)(row0 + m) * DD + k0 + k4);
        }
#pragma unroll
        for (int i = 0; i < 2; ++i) {
            int f4 = t + 128 * i;
            int l = f4 >> 3, k4 = (f4 & 7) << 2;
            wR[i] = *(const float4*)(W + (size_t)l * DD + k0 + k4);
        }
    };
    auto sts_tile = [&](int buf) {
#pragma unroll
        for (int i = 0; i < 4; ++i) {
            int f4 = t + 128 * i;
            int m = f4 >> 3, k4 = (f4 & 7) << 2;
            As[buf][k4 + 0][m] = aR[i].x;
            As[buf][k4 + 1][m] = aR[i].y;
            As[buf][k4 + 2][m] = aR[i].z;
            As[buf][k4 + 3][m] = aR[i].w;
        }
#pragma unroll
        for (int i = 0; i < 2; ++i) {
            int f4 = t + 128 * i;
            int l = f4 >> 3, k4 = (f4 & 7) << 2;
            Ws[buf][k4 + 0][l] = wR[i].x;
            Ws[buf][k4 + 1][l] = wR[i].y;
            Ws[buf][k4 + 2][l] = wR[i].z;
            Ws[buf][k4 + 3][l] = wR[i].w;
        }
    };

    unsigned long long acc[4][2];
#pragma unroll
    for (int i = 0; i < 4; ++i) { acc[i][0] = 0ull; acc[i][1] = 0ull; }

    ldg_tile(0);
    sts_tile(0);
    ldg_tile(BK);         // tile 1 staged in regs
    __syncthreads();

    const int NT = DD / BK;   // 32 tiles
    for (int it = 0; it < NT; ++it) {
        const int buf = it & 1;
#pragma unroll
        for (int kk = 0; kk < BK; ++kk) {
            float4 av = *(const float4*)&As[buf][kk][tm * 4];
            ulonglong2 wv = *(const ulonglong2*)&Ws[buf][kk][tn * 4];
            unsigned long long a0 = dup2(av.x), a1 = dup2(av.y),
                               a2 = dup2(av.z), a3 = dup2(av.w);
            fma2(acc[0][0], a0, wv.x); fma2(acc[0][1], a0, wv.y);
            fma2(acc[1][0], a1, wv.x); fma2(acc[1][1], a1, wv.y);
            fma2(acc[2][0], a2, wv.x); fma2(acc[2][1], a2, wv.y);
            fma2(acc[3][0], a3, wv.x); fma2(acc[3][1], a3, wv.y);
        }
        if (it + 1 < NT) {
            sts_tile(buf ^ 1);                    // stage tile it+1
            if (it + 2 < NT) ldg_tile((it + 2) * BK);
        }
        __syncthreads();
    }

    float4 bv = *(const float4*)&bias[tn * 4];
#pragma unroll
    for (int i = 0; i < 4; ++i) {
        int row = row0 + tm * 4 + i;
        float2 c01 = unpack2(acc[i][0]);
        float2 c23 = unpack2(acc[i][1]);
        float4 o;
        o.x = __expf(c01.x + bv.x);
        o.y = __expf(c01.y + bv.y);
        o.z = __expf(c23.x + bv.z);
        o.w = __expf(c23.y + bv.w);
        *(float4*)&g_q[(size_t)row * LL + tn * 4] = o;
    }
}

// ---------------------------------------------------------------------------
// Kernel 2: CRF scan. Warp 0: linear-space forward recurrence with smem
// p-vector (no SHFL on the chain). Warp 1: gold-path numerator (parallel).
// ---------------------------------------------------------------------------
#define SCAN_SMEM_FLOATS (TT * LL + LL * LL + TT + 64 + 8)
#define SCAN_SMEM_BYTES  (SCAN_SMEM_FLOATS * 4)

__global__ void __launch_bounds__(128) crf_scan(const float* __restrict__ start_t,
                                                const float* __restrict__ end_t,
                                                const float* __restrict__ trans,
                                                const int* __restrict__ labels) {
    extern __shared__ __align__(16) float sm[];
    float* Qs = sm;                            // [TT][LL]
    float* Ts = sm + TT * LL;                  // [LL][LL]
    int*   Ls = (int*)(Ts + LL * LL);          // [TT]
    float* pb = (float*)(Ls + TT);             // [2][32] p double buffer
    float* res = pb + 64;                      // [0]=num, [1]=den

    const int b = blockIdx.x;
    const int t = threadIdx.x;
    const int w = t >> 5;
    const int j = t & 31;
    const unsigned FULL = 0xffffffffu;

    // cooperative stage-in
    {
        const float4* src = (const float4*)(g_q + (size_t)b * TT * LL);
        float4* dst = (float4*)Qs;
#pragma unroll
        for (int i = 0; i < (TT * LL) / (128 * 4); ++i)
            dst[t + 128 * i] = src[t + 128 * i];
        ((float4*)Ts)[t]       = ((const float4*)trans)[t];
        ((float4*)Ts)[t + 128] = ((const float4*)trans)[t + 128];
        ((int4*)Ls)[t] = ((const int4*)(labels + b * TT))[t];
    }
    __syncthreads();

    if (w == 0) {
        // packed E columns: Ec[r] = (exp(T[2r][j]), exp(T[2r+1][j]))
        unsigned long long Ec[16];
#pragma unroll
        for (int r = 0; r < 16; ++r)
            Ec[r] = pack2(__expf(Ts[(2 * r) * LL + j]),
                          __expf(Ts[(2 * r + 1) * LL + j]));
        const float Eend = __expf(end_t[j]);

        float p0 = __expf(start_t[j]) * Qs[j];
        pb[j] = p0;
        __syncwarp(FULL);

        float logC = 0.0f;
        float qn = Qs[LL + j];
        float pj = p0;

#pragma unroll 2
        for (int tt = 1; tt < TT; ++tt) {
            const float* cur = pb + (((tt - 1) & 1) << 5);
            float* nxt = pb + ((tt & 1) << 5);

            float q = qn;
            int tnx = (tt + 1 < TT) ? (tt + 1) : tt;
            qn = Qs[tnx * LL + j];

            // renorm scalar path (off the fma chain)
            float r0 = cur[0];
            float rinv;
            asm("rcp.approx.f32 %0, %1;" : "=f"(rinv) : "f"(r0));
            logC += __logf(r0);
            float qr = q * rinv;

            // dot(p, Ecol_j) with packed fma
            ulonglong2 v0 = ((const ulonglong2*)cur)[0];
            ulonglong2 v1 = ((const ulonglong2*)cur)[1];
            ulonglong2 v2 = ((const ulonglong2*)cur)[2];
            ulonglong2 v3 = ((const ulonglong2*)cur)[3];
            ulonglong2 v4 = ((const ulonglong2*)cur)[4];
            ulonglong2 v5 = ((const ulonglong2*)cur)[5];
            ulonglong2 v6 = ((const ulonglong2*)cur)[6];
            ulonglong2 v7 = ((const ulonglong2*)cur)[7];

            unsigned long long s0 = 0ull, s1 = 0ull, s2 = 0ull, s3 = 0ull;
            fma2(s0, v0.x, Ec[0]);  fma2(s1, v0.y, Ec[1]);
            fma2(s2, v1.x, Ec[2]);  fma2(s3, v1.y, Ec[3]);
            fma2(s0, v2.x, Ec[4]);  fma2(s1, v2.y, Ec[5]);
            fma2(s2, v3.x, Ec[6]);  fma2(s3, v3.y, Ec[7]);
            fma2(s0, v4.x, Ec[8]);  fma2(s1, v4.y, Ec[9]);
            fma2(s2, v5.x, Ec[10]); fma2(s3, v5.y, Ec[11]);
            fma2(s0, v6.x, Ec[12]); fma2(s1, v6.y, Ec[13]);
            fma2(s2, v7.x, Ec[14]); fma2(s3, v7.y, Ec[15]);

            unsigned long long ss = add2(add2(s0, s1), add2(s2, s3));
            float2 sf = unpack2(ss);
            pj = (sf.x + sf.y) * qr;

            nxt[j] = pj;
            __syncwarp(FULL);
        }

        // den = logC + log(sum_j p_j * exp(end_j))
        float v = pj * Eend;
#pragma unroll
        for (int o = 16; o; o >>= 1) v += __shfl_xor_sync(FULL, v, o);
        float den = logC + __logf(v);
        if (j == 0) res[1] = den;
    } else if (w == 1) {
        // gold-path numerator, parallel over time
        float acc = 0.0f;
        for (int tt = j + 1; tt < TT; tt += 32) {
            int lp = Ls[tt - 1], lt = Ls[tt];
            acc += Ts[lp * LL + lt] + __logf(Qs[tt * LL + lt]);
        }
#pragma unroll
        for (int o = 16; o; o >>= 1) acc += __shfl_xor_sync(FULL, acc, o);
        if (j == 0) {
            int l0 = Ls[0], lT = Ls[TT - 1];
            res[0] = acc + start_t[l0] + __logf(Qs[l0]) + end_t[lT];
        }
    }
    __syncthreads();
    if (t == 0) g_nll[b] = res[1] - res[0];
}

// ---------------------------------------------------------------------------
// Kernel 3: mean over batch -> scalar
// ---------------------------------------------------------------------------
__global__ void __launch_bounds__(32) finalize(float* __restrict__ out) {
    const unsigned FULL = 0xffffffffu;
    int j = threadIdx.x;
    float v = g_nll[j] + g_nll[j + 32];
#pragma unroll
    for (int o = 16; o; o >>= 1) v += __shfl_xor_sync(FULL, v, o);
    if (j == 0) out[0] = v * (1.0f / (float)BB);
}

// ---------------------------------------------------------------------------
extern "C" void kernel_launch(void* const* d_in, const int* in_sizes, int n_in,
                              void* d_out, int out_size) {
    const float* emb    = (const float*)d_in[0];
    const float* W      = (const float*)d_in[1];
    const float* bias   = (const float*)d_in[2];
    const float* startt = (const float*)d_in[3];
    const float* endt   = (const float*)d_in[4];
    const float* trans  = (const float*)d_in[5];
    const int*   labels = (const int*)d_in[6];

    static int smem_set = 0;
    if (!smem_set) {
        cudaFuncSetAttribute(crf_scan, cudaFuncAttributeMaxDynamicSharedMemorySize,
                             SCAN_SMEM_BYTES);
        smem_set = 1;
    }

    emis_kernel<<<(BB * TT) / BM, 128>>>(emb, W, bias);
    crf_scan<<<BB, 128, SCAN_SMEM_BYTES>>>(startt, endt, trans, labels);
    finalize<<<1, 32>>>((float*)d_out);
}

// round 7
// speedup vs baseline: 3.5152x; 1.5490x over previous
#include <cuda_runtime.h>
#include <cuda_bf16.h>
#include <cstdint>

#define BB 64
#define TT 512
#define DD 1024
#define LL 32

__device__ float g_q[BB * TT * LL];   // 4 MB: exp(emissions)
__device__ float g_nll[BB];

// ---------------------------------------------------------------------------
// packed f32x2 helpers (scan kernel)
// ---------------------------------------------------------------------------
__device__ __forceinline__ void fma2(unsigned long long& d, unsigned long long a,
                                     unsigned long long b) {
    asm("fma.rn.f32x2 %0, %1, %2, %0;" : "+l"(d) : "l"(a), "l"(b));
}
__device__ __forceinline__ unsigned long long add2(unsigned long long a,
                                                   unsigned long long b) {
    unsigned long long r;
    asm("add.rn.f32x2 %0, %1, %2;" : "=l"(r) : "l"(a), "l"(b));
    return r;
}
__device__ __forceinline__ unsigned long long pack2(float lo, float hi) {
    unsigned long long r;
    asm("mov.b64 %0, {%1, %2};" : "=l"(r) : "f"(lo), "f"(hi));
    return r;
}
__device__ __forceinline__ float2 unpack2(unsigned long long v) {
    float2 f;
    asm("mov.b64 {%0, %1}, %2;" : "=f"(f.x), "=f"(f.y) : "l"(v));
    return f;
}

// ---------------------------------------------------------------------------
// tf32 helpers (GEMM kernel)
// ---------------------------------------------------------------------------
__device__ __forceinline__ uint32_t rna(float x) {   // unbiased round to tf32
    uint32_t r;
    asm("cvt.rna.tf32.f32 %0, %1;" : "=r"(r) : "f"(x));
    return r;
}
__device__ __forceinline__ void mma_tf32(float* c,
                                         uint32_t a0, uint32_t a1,
                                         uint32_t a2, uint32_t a3,
                                         uint32_t b0, uint32_t b1) {
    asm volatile(
        "mma.sync.aligned.m16n8k8.row.col.f32.tf32.tf32.f32 "
        "{%0,%1,%2,%3}, {%4,%5,%6,%7}, {%8,%9}, {%0,%1,%2,%3};"
        : "+f"(c[0]), "+f"(c[1]), "+f"(c[2]), "+f"(c[3])
        : "r"(a0), "r"(a1), "r"(a2), "r"(a3), "r"(b0), "r"(b1));
}

// ---------------------------------------------------------------------------
// Kernel 1: emissions GEMM via mma.sync tf32.
// q[row, l] = exp(A[row,:]·W[l,:] + bias[l]),  rows = B*T = 32768, L = 32.
// 256 threads (8 warps): warp w computes rows 16w..16w+15 x all 32 cols.
// K chunks of 32, LDG->cvt.rna->STS double buffering, EAP=36 padding
// (bank = 4*g + tig, conflict-free fragment LDS).
// ---------------------------------------------------------------------------
#define EAP 36
#define NT  (DD / 32)   // 32 k-chunks

__global__ void __launch_bounds__(256) emis_mma(const float* __restrict__ A,
                                                const float* __restrict__ W,
                                                const float* __restrict__ bias) {
    __shared__ __align__(16) uint32_t As[2][128 * EAP];  // [m][k] tf32 bits
    __shared__ __align__(16) uint32_t Ws[2][LL * EAP];   // [n][k] tf32 bits
    __shared__ float bs[LL];

    const int t    = threadIdx.x;
    const int w    = t >> 5;
    const int lane = t & 31;
    const int g    = lane >> 2;   // group 0..7
    const int tig  = lane & 3;    // thread-in-group 0..3
    const int row0 = blockIdx.x * 128;

    if (t < LL) bs[t] = bias[t];

    float4 aR[4];
    float4 wR;

    auto ldg = [&](int k0) {
#pragma unroll
        for (int i = 0; i < 4; ++i) {
            int seg = t + 256 * i;          // 0..1023
            int m = seg >> 3, kq = seg & 7; // row, float4-slot
            aR[i] = *(const float4*)(A + (size_t)(row0 + m) * DD + k0 + kq * 4);
        }
        {
            int n = t >> 3, kq = t & 7;     // 32 rows x 8 float4 = 256
            wR = *(const float4*)(W + (size_t)n * DD + k0 + kq * 4);
        }
    };
    auto sts = [&](int buf) {
#pragma unroll
        for (int i = 0; i < 4; ++i) {
            int seg = t + 256 * i;
            int m = seg >> 3, kq = seg & 7;
            uint4 u;
            u.x = rna(aR[i].x); u.y = rna(aR[i].y);
            u.z = rna(aR[i].z); u.w = rna(aR[i].w);
            *(uint4*)&As[buf][m * EAP + kq * 4] = u;
        }
        {
            int n = t >> 3, kq = t & 7;
            uint4 u;
            u.x = rna(wR.x); u.y = rna(wR.y); u.z = rna(wR.z); u.w = rna(wR.w);
            *(uint4*)&Ws[buf][n * EAP + kq * 4] = u;
        }
    };

    float acc[4][4];   // [n-frag][c0..c3]
#pragma unroll
    for (int nf = 0; nf < 4; ++nf)
#pragma unroll
        for (int i = 0; i < 4; ++i) acc[nf][i] = 0.0f;

    ldg(0);
    sts(0);
    ldg(32);
    __syncthreads();

    const int rA0 = (16 * w + g) * EAP;        // row g
    const int rA1 = (16 * w + g + 8) * EAP;    // row g+8

    for (int it = 0; it < NT; ++it) {
        const int buf = it & 1;
        const uint32_t* __restrict__ as = As[buf];
        const uint32_t* __restrict__ ws = Ws[buf];
#pragma unroll
        for (int ks = 0; ks < 4; ++ks) {
            const int k = ks * 8;
            uint32_t a0 = as[rA0 + k + tig];
            uint32_t a1 = as[rA1 + k + tig];
            uint32_t a2 = as[rA0 + k + tig + 4];
            uint32_t a3 = as[rA1 + k + tig + 4];
#pragma unroll
            for (int nf = 0; nf < 4; ++nf) {
                uint32_t b0 = ws[(nf * 8 + g) * EAP + k + tig];
                uint32_t b1 = ws[(nf * 8 + g) * EAP + k + tig + 4];
                mma_tf32(acc[nf], a0, a1, a2, a3, b0, b1);
            }
        }
        if (it + 1 < NT) {
            sts(buf ^ 1);
            if (it + 2 < NT) ldg((it + 2) * 32);
        }
        __syncthreads();
    }

    // epilogue: q = exp(acc + bias)
    const int r0 = row0 + 16 * w + g;
#pragma unroll
    for (int nf = 0; nf < 4; ++nf) {
        const int n = nf * 8 + 2 * tig;
        float b0 = bs[n], b1 = bs[n + 1];
        float2 v0, v1;
        v0.x = __expf(acc[nf][0] + b0);
        v0.y = __expf(acc[nf][1] + b1);
        v1.x = __expf(acc[nf][2] + b0);
        v1.y = __expf(acc[nf][3] + b1);
        *(float2*)&g_q[(size_t)r0 * LL + n]       = v0;
        *(float2*)&g_q[(size_t)(r0 + 8) * LL + n] = v1;
    }
}

// ---------------------------------------------------------------------------
// Kernel 2: CRF scan (proven R3 version). Warp 0: linear-space recurrence via
// smem p double-buffer; warp 1: gold-path numerator in parallel.
// ---------------------------------------------------------------------------
#define SCAN_SMEM_FLOATS (TT * LL + LL * LL + TT + 64 + 8)
#define SCAN_SMEM_BYTES  (SCAN_SMEM_FLOATS * 4)

__global__ void __launch_bounds__(128) crf_scan(const float* __restrict__ start_t,
                                                const float* __restrict__ end_t,
                                                const float* __restrict__ trans,
                                                const int* __restrict__ labels) {
    extern __shared__ __align__(16) float smf[];
    float* Qs = smf;                           // [TT][LL]
    float* Ts = smf + TT * LL;                 // [LL][LL]
    int*   Ls = (int*)(Ts + LL * LL);          // [TT]
    float* pb = (float*)(Ls + TT);             // [2][32]
    float* res = pb + 64;                      // [0]=num, [1]=den

    const int b = blockIdx.x;
    const int t = threadIdx.x;
    const int w = t >> 5;
    const int j = t & 31;
    const unsigned FULL = 0xffffffffu;

    {
        const float4* src = (const float4*)(g_q + (size_t)b * TT * LL);
        float4* dst = (float4*)Qs;
#pragma unroll
        for (int i = 0; i < (TT * LL) / (128 * 4); ++i)
            dst[t + 128 * i] = src[t + 128 * i];
        ((float4*)Ts)[t]       = ((const float4*)trans)[t];
        ((float4*)Ts)[t + 128] = ((const float4*)trans)[t + 128];
        ((int4*)Ls)[t] = ((const int4*)(labels + b * TT))[t];
    }
    __syncthreads();

    if (w == 0) {
        unsigned long long Ec[16];
#pragma unroll
        for (int r = 0; r < 16; ++r)
            Ec[r] = pack2(__expf(Ts[(2 * r) * LL + j]),
                          __expf(Ts[(2 * r + 1) * LL + j]));
        const float Eend = __expf(end_t[j]);

        float p0 = __expf(start_t[j]) * Qs[j];
        pb[j] = p0;
        __syncwarp(FULL);

        float logC = 0.0f;
        float qn = Qs[LL + j];
        float pj = p0;

#pragma unroll 2
        for (int tt = 1; tt < TT; ++tt) {
            const float* cur = pb + (((tt - 1) & 1) << 5);
            float* nxt = pb + ((tt & 1) << 5);

            float q = qn;
            int tnx = (tt + 1 < TT) ? (tt + 1) : tt;
            qn = Qs[tnx * LL + j];

            float r0 = cur[0];
            float rinv;
            asm("rcp.approx.f32 %0, %1;" : "=f"(rinv) : "f"(r0));
            logC += __logf(r0);
            float qr = q * rinv;

            ulonglong2 v0 = ((const ulonglong2*)cur)[0];
            ulonglong2 v1 = ((const ulonglong2*)cur)[1];
            ulonglong2 v2 = ((const ulonglong2*)cur)[2];
            ulonglong2 v3 = ((const ulonglong2*)cur)[3];
            ulonglong2 v4 = ((const ulonglong2*)cur)[4];
            ulonglong2 v5 = ((const ulonglong2*)cur)[5];
            ulonglong2 v6 = ((const ulonglong2*)cur)[6];
            ulonglong2 v7 = ((const ulonglong2*)cur)[7];

            unsigned long long s0 = 0ull, s1 = 0ull, s2 = 0ull, s3 = 0ull;
            fma2(s0, v0.x, Ec[0]);  fma2(s1, v0.y, Ec[1]);
            fma2(s2, v1.x, Ec[2]);  fma2(s3, v1.y, Ec[3]);
            fma2(s0, v2.x, Ec[4]);  fma2(s1, v2.y, Ec[5]);
            fma2(s2, v3.x, Ec[6]);  fma2(s3, v3.y, Ec[7]);
            fma2(s0, v4.x, Ec[8]);  fma2(s1, v4.y, Ec[9]);
            fma2(s2, v5.x, Ec[10]); fma2(s3, v5.y, Ec[11]);
            fma2(s0, v6.x, Ec[12]); fma2(s1, v6.y, Ec[13]);
            fma2(s2, v7.x, Ec[14]); fma2(s3, v7.y, Ec[15]);

            unsigned long long ss = add2(add2(s0, s1), add2(s2, s3));
            float2 sf = unpack2(ss);
            pj = (sf.x + sf.y) * qr;

            nxt[j] = pj;
            __syncwarp(FULL);
        }

        float v = pj * Eend;
#pragma unroll
        for (int o = 16; o; o >>= 1) v += __shfl_xor_sync(FULL, v, o);
        float den = logC + __logf(v);
        if (j == 0) res[1] = den;
    } else if (w == 1) {
        float acc = 0.0f;
        for (int tt = j + 1; tt < TT; tt += 32) {
            int lp = Ls[tt - 1], lt = Ls[tt];
            acc += Ts[lp * LL + lt] + __logf(Qs[tt * LL + lt]);
        }
#pragma unroll
        for (int o = 16; o; o >>= 1) acc += __shfl_xor_sync(FULL, acc, o);
        if (j == 0) {
            int l0 = Ls[0], lT = Ls[TT - 1];
            res[0] = acc + start_t[l0] + __logf(Qs[l0]) + end_t[lT];
        }
    }
    __syncthreads();
    if (t == 0) g_nll[b] = res[1] - res[0];
}

// ---------------------------------------------------------------------------
// Kernel 3: mean over batch -> scalar
// ---------------------------------------------------------------------------
__global__ void __launch_bounds__(32) finalize(float* __restrict__ out) {
    const unsigned FULL = 0xffffffffu;
    int j = threadIdx.x;
    float v = g_nll[j] + g_nll[j + 32];
#pragma unroll
    for (int o = 16; o; o >>= 1) v += __shfl_xor_sync(FULL, v, o);
    if (j == 0) out[0] = v * (1.0f / (float)BB);
}

// ---------------------------------------------------------------------------
extern "C" void kernel_launch(void* const* d_in, const int* in_sizes, int n_in,
                              void* d_out, int out_size) {
    const float* emb    = (const float*)d_in[0];
    const float* W      = (const float*)d_in[1];
    const float* bias   = (const float*)d_in[2];
    const float* startt = (const float*)d_in[3];
    const float* endt   = (const float*)d_in[4];
    const float* trans  = (const float*)d_in[5];
    const int*   labels = (const int*)d_in[6];

    static int attr_set = 0;
    if (!attr_set) {
        cudaFuncSetAttribute(crf_scan, cudaFuncAttributeMaxDynamicSharedMemorySize,
                             SCAN_SMEM_BYTES);
        attr_set = 1;
    }

    emis_mma<<<(BB * TT) / 128, 256>>>(emb, W, bias);
    crf_scan<<<BB, 128, SCAN_SMEM_BYTES>>>(startt, endt, trans, labels);
    finalize<<<1, 32>>>((float*)d_out);
}

// round 8
// speedup vs baseline: 3.7999x; 1.0810x over previous
#include <cuda_runtime.h>
#include <cuda_bf16.h>
#include <cstdint>

#define BB 64
#define TT 512
#define DD 1024
#define LL 32
#define CH 16    // chunks per sequence
#define CL 32    // steps per chunk

__device__ float g_q[BB * TT * LL];          // 4 MB: exp(emissions)
__device__ float g_cm[BB * CH * LL * LL];    // 4 MB: chunk product matrices
__device__ float g_cex[BB * CH];             // chunk log-scales
__device__ float g_nll[BB];

// ---------------------------------------------------------------------------
// tf32 / mma helpers
// ---------------------------------------------------------------------------
__device__ __forceinline__ uint32_t rna(float x) {   // unbiased round to tf32
    uint32_t r;
    asm("cvt.rna.tf32.f32 %0, %1;" : "=r"(r) : "f"(x));
    return r;
}
__device__ __forceinline__ void mma_tf32(float* c,
                                         uint32_t a0, uint32_t a1,
                                         uint32_t a2, uint32_t a3,
                                         uint32_t b0, uint32_t b1) {
    asm volatile(
        "mma.sync.aligned.m16n8k8.row.col.f32.tf32.tf32.f32 "
        "{%0,%1,%2,%3}, {%4,%5,%6,%7}, {%8,%9}, {%0,%1,%2,%3};"
        : "+f"(c[0]), "+f"(c[1]), "+f"(c[2]), "+f"(c[3])
        : "r"(a0), "r"(a1), "r"(a2), "r"(a3), "r"(b0), "r"(b1));
}

// ---------------------------------------------------------------------------
// Kernel 1: emissions GEMM via mma.sync tf32 (proven R7 version).
// ---------------------------------------------------------------------------
#define EAP 36
#define NT  (DD / 32)

__global__ void __launch_bounds__(256) emis_mma(const float* __restrict__ A,
                                                const float* __restrict__ W,
                                                const float* __restrict__ bias) {
    __shared__ __align__(16) uint32_t As[2][128 * EAP];
    __shared__ __align__(16) uint32_t Ws[2][LL * EAP];
    __shared__ float bs[LL];

    const int t    = threadIdx.x;
    const int w    = t >> 5;
    const int lane = t & 31;
    const int g    = lane >> 2;
    const int tig  = lane & 3;
    const int row0 = blockIdx.x * 128;

    if (t < LL) bs[t] = bias[t];

    float4 aR[4];
    float4 wR;

    auto ldg = [&](int k0) {
#pragma unroll
        for (int i = 0; i < 4; ++i) {
            int seg = t + 256 * i;
            int m = seg >> 3, kq = seg & 7;
            aR[i] = *(const float4*)(A + (size_t)(row0 + m) * DD + k0 + kq * 4);
        }
        {
            int n = t >> 3, kq = t & 7;
            wR = *(const float4*)(W + (size_t)n * DD + k0 + kq * 4);
        }
    };
    auto sts = [&](int buf) {
#pragma unroll
        for (int i = 0; i < 4; ++i) {
            int seg = t + 256 * i;
            int m = seg >> 3, kq = seg & 7;
            uint4 u;
            u.x = rna(aR[i].x); u.y = rna(aR[i].y);
            u.z = rna(aR[i].z); u.w = rna(aR[i].w);
            *(uint4*)&As[buf][m * EAP + kq * 4] = u;
        }
        {
            int n = t >> 3, kq = t & 7;
            uint4 u;
            u.x = rna(wR.x); u.y = rna(wR.y); u.z = rna(wR.z); u.w = rna(wR.w);
            *(uint4*)&Ws[buf][n * EAP + kq * 4] = u;
        }
    };

    float acc[4][4];
#pragma unroll
    for (int nf = 0; nf < 4; ++nf)
#pragma unroll
        for (int i = 0; i < 4; ++i) acc[nf][i] = 0.0f;

    ldg(0);
    sts(0);
    ldg(32);
    __syncthreads();

    const int rA0 = (16 * w + g) * EAP;
    const int rA1 = (16 * w + g + 8) * EAP;

    for (int it = 0; it < NT; ++it) {
        const int buf = it & 1;
        const uint32_t* __restrict__ as = As[buf];
        const uint32_t* __restrict__ ws = Ws[buf];
#pragma unroll
        for (int ks = 0; ks < 4; ++ks) {
            const int k = ks * 8;
            uint32_t a0 = as[rA0 + k + tig];
            uint32_t a1 = as[rA1 + k + tig];
            uint32_t a2 = as[rA0 + k + tig + 4];
            uint32_t a3 = as[rA1 + k + tig + 4];
#pragma unroll
            for (int nf = 0; nf < 4; ++nf) {
                uint32_t b0 = ws[(nf * 8 + g) * EAP + k + tig];
                uint32_t b1 = ws[(nf * 8 + g) * EAP + k + tig + 4];
                mma_tf32(acc[nf], a0, a1, a2, a3, b0, b1);
            }
        }
        if (it + 1 < NT) {
            sts(buf ^ 1);
            if (it + 2 < NT) ldg((it + 2) * 32);
        }
        __syncthreads();
    }

    const int r0 = row0 + 16 * w + g;
#pragma unroll
    for (int nf = 0; nf < 4; ++nf) {
        const int n = nf * 8 + 2 * tig;
        float b0 = bs[n], b1 = bs[n + 1];
        float2 v0, v1;
        v0.x = __expf(acc[nf][0] + b0);
        v0.y = __expf(acc[nf][1] + b1);
        v1.x = __expf(acc[nf][2] + b0);
        v1.y = __expf(acc[nf][3] + b1);
        *(float2*)&g_q[(size_t)r0 * LL + n]       = v0;
        *(float2*)&g_q[(size_t)(r0 + 8) * LL + n] = v1;
    }
}

// ---------------------------------------------------------------------------
// Kernel 2: chunk matrix products. Block = 1 warp = (seq b, chunk c).
// C <- diag(q_t) * (E^T * C) iterated over the chunk, via mma.sync tf32.
// E^T fragments pinned in registers; C round-trips through smem (stride 40:
// B-fragment LDS banks = 8*tig+g, conflict-free). Max-renorm every 4 steps.
// ---------------------------------------------------------------------------
#define CP 40   // Cs/ET row stride (floats)

__global__ void __launch_bounds__(32) crf_chunk(const float* __restrict__ trans) {
    __shared__ float ET[32 * CP];     // E^T, tf32-rounded
    __shared__ float Cs[32 * CP];     // running product
    __shared__ float qs[CL * 32];     // q rows for this chunk

    const int bid = blockIdx.x;
    const int b = bid >> 4, c = bid & 15;
    const int lane = threadIdx.x;
    const int g = lane >> 2, tig = lane & 3;
    const unsigned FULL = 0xffffffffu;

    // stage q rows [c*32, c*32+32)
    {
        const float4* src = (const float4*)(g_q + ((size_t)b * TT + c * CL) * LL);
        float4* dst = (float4*)qs;
#pragma unroll
        for (int i = 0; i < (CL * 32) / (32 * 4); ++i)
            dst[lane + 32 * i] = src[lane + 32 * i];
    }
    // ET[r][l] = rna(exp(trans[l][r])); lane l writes column l
#pragma unroll
    for (int r = 0; r < 32; ++r)
        ET[r * CP + lane] = __uint_as_float(rna(__expf(trans[lane * 32 + r])));
    __syncwarp();

    // A fragments (E^T), constant for the whole chunk
    uint32_t Af[2][4][4];
#pragma unroll
    for (int i = 0; i < 2; ++i)
#pragma unroll
        for (int kc = 0; kc < 4; ++kc) {
            Af[i][kc][0] = __float_as_uint(ET[(16 * i + g) * CP + 8 * kc + tig]);
            Af[i][kc][1] = __float_as_uint(ET[(16 * i + g + 8) * CP + 8 * kc + tig]);
            Af[i][kc][2] = __float_as_uint(ET[(16 * i + g) * CP + 8 * kc + tig + 4]);
            Af[i][kc][3] = __float_as_uint(ET[(16 * i + g + 8) * CP + 8 * kc + tig + 4]);
        }

    // init C = M_{t0}: C[r][l] = rna(q0[r] * ET[r][l])
    const int ls0 = (c == 0) ? 1 : 0;
    {
        const float* q0 = qs + ls0 * 32;
#pragma unroll
        for (int r = 0; r < 32; ++r)
            Cs[r * CP + lane] = __uint_as_float(rna(q0[r] * ET[r * CP + lane]));
    }
    __syncwarp();

    float logC = 0.0f;
    for (int ls = ls0 + 1; ls < CL; ++ls) {
        // B fragments from current C
        uint32_t Bf[4][4][2];
#pragma unroll
        for (int kc = 0; kc < 4; ++kc)
#pragma unroll
            for (int nt = 0; nt < 4; ++nt) {
                Bf[kc][nt][0] = __float_as_uint(Cs[(8 * kc + tig) * CP + 8 * nt + g]);
                Bf[kc][nt][1] = __float_as_uint(Cs[(8 * kc + tig + 4) * CP + 8 * nt + g]);
            }

        float acc[2][4][4];
#pragma unroll
        for (int i = 0; i < 2; ++i)
#pragma unroll
            for (int nt = 0; nt < 4; ++nt)
#pragma unroll
                for (int v = 0; v < 4; ++v) acc[i][nt][v] = 0.0f;

#pragma unroll
        for (int i = 0; i < 2; ++i)
#pragma unroll
            for (int kc = 0; kc < 4; ++kc)
#pragma unroll
                for (int nt = 0; nt < 4; ++nt)
                    mma_tf32(acc[i][nt],
                             Af[i][kc][0], Af[i][kc][1], Af[i][kc][2], Af[i][kc][3],
                             Bf[kc][nt][0], Bf[kc][nt][1]);

        // row-scale by q_t
        const float* qr = qs + ls * 32;
#pragma unroll
        for (int i = 0; i < 2; ++i) {
            float qa = qr[16 * i + g];
            float qb = qr[16 * i + g + 8];
#pragma unroll
            for (int nt = 0; nt < 4; ++nt) {
                acc[i][nt][0] *= qa; acc[i][nt][1] *= qa;
                acc[i][nt][2] *= qb; acc[i][nt][3] *= qb;
            }
        }

        // periodic renorm (and always on the final step)
        if ((ls & 3) == 3 || ls == CL - 1) {
            float m = acc[0][0][0];
#pragma unroll
            for (int i = 0; i < 2; ++i)
#pragma unroll
                for (int nt = 0; nt < 4; ++nt)
#pragma unroll
                    for (int v = 0; v < 4; ++v) m = fmaxf(m, acc[i][nt][v]);
#pragma unroll
            for (int o = 16; o; o >>= 1) m = fmaxf(m, __shfl_xor_sync(FULL, m, o));
            float rinv;
            asm("rcp.approx.f32 %0, %1;" : "=f"(rinv) : "f"(m));
            logC += __logf(m);
#pragma unroll
            for (int i = 0; i < 2; ++i)
#pragma unroll
                for (int nt = 0; nt < 4; ++nt)
#pragma unroll
                    for (int v = 0; v < 4; ++v) acc[i][nt][v] *= rinv;
        }

        // store back (tf32-rounded) for the next step's B fragments
#pragma unroll
        for (int i = 0; i < 2; ++i)
#pragma unroll
            for (int nt = 0; nt < 4; ++nt) {
                uint32_t u0 = rna(acc[i][nt][0]), u1 = rna(acc[i][nt][1]);
                uint32_t u2 = rna(acc[i][nt][2]), u3 = rna(acc[i][nt][3]);
                uint2 p01 = make_uint2(u0, u1), p23 = make_uint2(u2, u3);
                *(uint2*)&Cs[(16 * i + g) * CP + 8 * nt + 2 * tig]     = p01;
                *(uint2*)&Cs[(16 * i + g + 8) * CP + 8 * nt + 2 * tig] = p23;
            }
        __syncwarp();
    }

    // write out C (coalesced rows) + log scale
    float* out = g_cm + (size_t)bid * (LL * LL);
#pragma unroll
    for (int r = 0; r < 32; ++r)
        out[r * 32 + lane] = Cs[r * CP + lane];
    if (lane == 0) g_cex[bid] = logC;
}

// ---------------------------------------------------------------------------
// Kernel 3: per-sequence combine. Warp 0: p0 -> 16 matvecs through chunk
// matrices (renorm each step). Warps 1-3: gold-path numerator in parallel.
// ---------------------------------------------------------------------------
#define CMP 33   // combine smem row stride
#define CMB_FLOATS (CH * LL * CMP + LL * LL + TT + 8)
#define CMB_SMEM   (CMB_FLOATS * 4)

__global__ void __launch_bounds__(128) crf_combine(const float* __restrict__ start_t,
                                                   const float* __restrict__ end_t,
                                                   const float* __restrict__ trans,
                                                   const int* __restrict__ labels) {
    extern __shared__ __align__(16) float smf[];
    float* Cm = smf;                              // [CH][32][CMP]
    float* Ts = Cm + CH * LL * CMP;               // [32][32]
    int*   Ls = (int*)(Ts + LL * LL);             // [TT]
    float* res = (float*)(Ls + TT);               // [0]=den, [1..3]=num parts

    const int b = blockIdx.x;
    const int t = threadIdx.x;
    const int w = t >> 5;
    const int j = t & 31;
    const unsigned FULL = 0xffffffffu;

    // stage chunk matrices (stride CMP), trans, labels
    {
        const float* src = g_cm + (size_t)b * CH * LL * LL;
        for (int idx = t; idx < CH * LL * LL; idx += 128) {
            int cc = idx >> 10, rem = idx & 1023;
            int r = rem >> 5, col = rem & 31;
            Cm[cc * (LL * CMP) + r * CMP + col] = src[idx];
        }
        ((float4*)Ts)[t]       = ((const float4*)trans)[t];
        ((float4*)Ts)[t + 128] = ((const float4*)trans)[t + 128];
        ((int4*)Ls)[t] = ((const int4*)(labels + b * TT))[t];
    }
    __syncthreads();

    if (w == 0) {
        const float Eend = __expf(end_t[j]);
        float p = __expf(start_t[j]) * g_q[(size_t)b * TT * LL + j];   // t=0

        float logC = (j < CH) ? g_cex[b * CH + j] : 0.0f;
#pragma unroll
        for (int o = 16; o; o >>= 1) logC += __shfl_xor_sync(FULL, logC, o);

#pragma unroll 1
        for (int c = 0; c < CH; ++c) {
            const float* Cc = Cm + c * (LL * CMP) + j * CMP;
            float s0 = 0.f, s1 = 0.f, s2 = 0.f, s3 = 0.f;
#pragma unroll
            for (int i = 0; i < 32; i += 4) {
                float p0 = __shfl_sync(FULL, p, i + 0);
                float p1 = __shfl_sync(FULL, p, i + 1);
                float p2 = __shfl_sync(FULL, p, i + 2);
                float p3 = __shfl_sync(FULL, p, i + 3);
                s0 = fmaf(p0, Cc[i + 0], s0);
                s1 = fmaf(p1, Cc[i + 1], s1);
                s2 = fmaf(p2, Cc[i + 2], s2);
                s3 = fmaf(p3, Cc[i + 3], s3);
            }
            float pn = (s0 + s1) + (s2 + s3);
            float m = pn;
#pragma unroll
            for (int o = 16; o; o >>= 1) m = fmaxf(m, __shfl_xor_sync(FULL, m, o));
            float rinv;
            asm("rcp.approx.f32 %0, %1;" : "=f"(rinv) : "f"(m));
            logC += __logf(m);
            p = pn * rinv;
        }

        float v = p * Eend;
#pragma unroll
        for (int o = 16; o; o >>= 1) v += __shfl_xor_sync(FULL, v, o);
        if (j == 0) res[0] = logC + __logf(v);
    } else {
        // numerator over t = 1..511, strided across warps 1-3
        float acc = 0.0f;
        const int gi = (w - 1) * 32 + j;
        for (int tt = 1 + gi; tt < TT; tt += 96) {
            int lp = Ls[tt - 1], lt = Ls[tt];
            acc += Ts[lp * LL + lt] + __logf(g_q[(size_t)b * TT * LL + tt * LL + lt]);
        }
#pragma unroll
        for (int o = 16; o; o >>= 1) acc += __shfl_xor_sync(FULL, acc, o);
        if (j == 0) res[w] = acc;
    }
    __syncthreads();
    if (t == 0) {
        int l0 = Ls[0], lT = Ls[TT - 1];
        float num = res[1] + res[2] + res[3]
                  + start_t[l0] + __logf(g_q[(size_t)b * TT * LL + l0])
                  + end_t[lT];
        g_nll[b] = res[0] - num;
    }
}

// ---------------------------------------------------------------------------
// Kernel 4: mean over batch -> scalar
// ---------------------------------------------------------------------------
__global__ void __launch_bounds__(32) finalize(float* __restrict__ out) {
    const unsigned FULL = 0xffffffffu;
    int j = threadIdx.x;
    float v = g_nll[j] + g_nll[j + 32];
#pragma unroll
    for (int o = 16; o; o >>= 1) v += __shfl_xor_sync(FULL, v, o);
    if (j == 0) out[0] = v * (1.0f / (float)BB);
}

// ---------------------------------------------------------------------------
extern "C" void kernel_launch(void* const* d_in, const int* in_sizes, int n_in,
                              void* d_out, int out_size) {
    const float* emb    = (const float*)d_in[0];
    const float* W      = (const float*)d_in[1];
    const float* bias   = (const float*)d_in[2];
    const float* startt = (const float*)d_in[3];
    const float* endt   = (const float*)d_in[4];
    const float* trans  = (const float*)d_in[5];
    const int*   labels = (const int*)d_in[6];

    static int attr_set = 0;
    if (!attr_set) {
        cudaFuncSetAttribute(crf_combine, cudaFuncAttributeMaxDynamicSharedMemorySize,
                             CMB_SMEM);
        attr_set = 1;
    }

    emis_mma<<<(BB * TT) / 128, 256>>>(emb, W, bias);
    crf_chunk<<<BB * CH, 32>>>(trans);
    crf_combine<<<BB, 128, CMB_SMEM>>>(startt, endt, trans, labels);
    finalize<<<1, 32>>>((float*)d_out);
}

// round 9
// speedup vs baseline: 4.9442x; 1.3011x over previous
#include <cuda_runtime.h>
#include <cuda_bf16.h>
#include <cstdint>

#define BB 64
#define TT 512
#define DD 1024
#define LL 32
#define CH 16    // chunks per sequence
#define CL 32    // steps per chunk

__device__ float g_q[BB * TT * LL];          // 4 MB: exp(emissions)
__device__ float g_cm[BB * CH * LL * LL];    // 4 MB: chunk product matrices
__device__ float g_cex[BB * CH];             // chunk log-scales
__device__ float g_nll[BB];
__device__ unsigned g_done;

// ---------------------------------------------------------------------------
// helpers
// ---------------------------------------------------------------------------
__device__ __forceinline__ uint32_t rna(float x) {   // unbiased round to tf32
    uint32_t r;
    asm("cvt.rna.tf32.f32 %0, %1;" : "=r"(r) : "f"(x));
    return r;
}
__device__ __forceinline__ void mma_tf32(float* c,
                                         uint32_t a0, uint32_t a1,
                                         uint32_t a2, uint32_t a3,
                                         uint32_t b0, uint32_t b1) {
    asm volatile(
        "mma.sync.aligned.m16n8k8.row.col.f32.tf32.tf32.f32 "
        "{%0,%1,%2,%3}, {%4,%5,%6,%7}, {%8,%9}, {%0,%1,%2,%3};"
        : "+f"(c[0]), "+f"(c[1]), "+f"(c[2]), "+f"(c[3])
        : "r"(a0), "r"(a1), "r"(a2), "r"(a3), "r"(b0), "r"(b1));
}
__device__ __forceinline__ void mma_bf16(float* c,
                                         uint32_t a0, uint32_t a1,
                                         uint32_t a2, uint32_t a3,
                                         uint32_t b0, uint32_t b1) {
    asm volatile(
        "mma.sync.aligned.m16n8k16.row.col.f32.bf16.bf16.f32 "
        "{%0,%1,%2,%3}, {%4,%5,%6,%7}, {%8,%9}, {%0,%1,%2,%3};"
        : "+f"(c[0]), "+f"(c[1]), "+f"(c[2]), "+f"(c[3])
        : "r"(a0), "r"(a1), "r"(a2), "r"(a3), "r"(b0), "r"(b1));
}
__device__ __forceinline__ uint32_t bf2pack(float hi, float lo) {
    uint32_t r;
    asm("cvt.rn.bf16x2.f32 %0, %1, %2;" : "=r"(r) : "f"(hi), "f"(lo));
    return r;
}

// ---------------------------------------------------------------------------
// Kernel 1: emissions GEMM, mma.sync tf32.
// M-tile 64, 128 threads (4 warps x 16 rows), grid 512.
// A: cp.async.cg 16B, 4-stage pipeline, raw fp32 (tf32-truncated by MMA).
// W: LDG -> cvt.rna -> STS, 2-stage (exact tf32 rounding; W is 32x smaller).
// ---------------------------------------------------------------------------
#define NSTG 4
#define APD  36
#define NT   (DD / 32)

__global__ void __launch_bounds__(128) emis_mma(const float* __restrict__ A,
                                                const float* __restrict__ W,
                                                const float* __restrict__ bias) {
    __shared__ __align__(16) float    As[NSTG][64 * APD];  // [m][k]
    __shared__ __align__(16) uint32_t Ws[2][LL * APD];     // [n][k] tf32 bits
    __shared__ float bs[LL];

    const int t    = threadIdx.x;
    const int w    = t >> 5;
    const int lane = t & 31;
    const int g    = lane >> 2;
    const int tig  = lane & 3;
    const int row0 = blockIdx.x * 64;

    if (t < LL) bs[t] = bias[t];

    auto a_issue = [&](int tile) {
        const int s = tile & (NSTG - 1);
        const int k0 = tile * 32;
#pragma unroll
        for (int i = 0; i < 4; ++i) {
            int idx = t + 128 * i;            // 0..511
            int m = idx >> 3, kq = idx & 7;
            uint32_t dst = (uint32_t)__cvta_generic_to_shared(&As[s][m * APD + kq * 4]);
            const float* src = A + (size_t)(row0 + m) * DD + k0 + kq * 4;
            asm volatile("cp.async.cg.shared.global [%0], [%1], 16;"
                         :: "r"(dst), "l"(src));
        }
        asm volatile("cp.async.commit_group;" ::: "memory");
    };

    float4 wR[2];
    auto w_ldg = [&](int tile) {
        const int k0 = tile * 32;
#pragma unroll
        for (int i = 0; i < 2; ++i) {
            int idx = t + 128 * i;            // 0..255
            int n = idx >> 3, kq = idx & 7;
            wR[i] = *(const float4*)(W + (size_t)n * DD + k0 + kq * 4);
        }
    };
    auto w_sts = [&](int buf) {
#pragma unroll
        for (int i = 0; i < 2; ++i) {
            int idx = t + 128 * i;
            int n = idx >> 3, kq = idx & 7;
            uint4 u;
            u.x = rna(wR[i].x); u.y = rna(wR[i].y);
            u.z = rna(wR[i].z); u.w = rna(wR[i].w);
            *(uint4*)&Ws[buf][n * APD + kq * 4] = u;
        }
    };

    a_issue(0); a_issue(1); a_issue(2);
    w_ldg(0); w_sts(0); w_ldg(1);

    float acc[4][4];
#pragma unroll
    for (int nf = 0; nf < 4; ++nf)
#pragma unroll
        for (int i = 0; i < 4; ++i) acc[nf][i] = 0.0f;

    const int rA0 = (16 * w + g) * APD;
    const int rA1 = (16 * w + g + 8) * APD;

    for (int it = 0; it < NT; ++it) {
        if (it <= NT - 3)
            asm volatile("cp.async.wait_group 2;" ::: "memory");
        else if (it == NT - 2)
            asm volatile("cp.async.wait_group 1;" ::: "memory");
        else
            asm volatile("cp.async.wait_group 0;" ::: "memory");
        __syncthreads();

        const float*    as = As[it & (NSTG - 1)];
        const uint32_t* ws = Ws[it & 1];
#pragma unroll
        for (int ks = 0; ks < 4; ++ks) {
            const int k = 8 * ks;
            uint32_t a0 = __float_as_uint(as[rA0 + k + tig]);
            uint32_t a1 = __float_as_uint(as[rA1 + k + tig]);
            uint32_t a2 = __float_as_uint(as[rA0 + k + tig + 4]);
            uint32_t a3 = __float_as_uint(as[rA1 + k + tig + 4]);
#pragma unroll
            for (int nf = 0; nf < 4; ++nf) {
                uint32_t b0 = ws[(8 * nf + g) * APD + k + tig];
                uint32_t b1 = ws[(8 * nf + g) * APD + k + tig + 4];
                mma_tf32(acc[nf], a0, a1, a2, a3, b0, b1);
            }
        }
        if (it + 1 < NT) {
            w_sts((it + 1) & 1);
            if (it + 2 < NT) w_ldg(it + 2);
            if (it + 3 < NT) a_issue(it + 3);
        }
    }

    // epilogue: q = exp(acc + bias)
    const int r0 = row0 + 16 * w + g;
#pragma unroll
    for (int nf = 0; nf < 4; ++nf) {
        const int n = nf * 8 + 2 * tig;
        float b0 = bs[n], b1 = bs[n + 1];
        float2 v0, v1;
        v0.x = __expf(acc[nf][0] + b0);
        v0.y = __expf(acc[nf][1] + b1);
        v1.x = __expf(acc[nf][2] + b0);
        v1.y = __expf(acc[nf][3] + b1);
        *(float2*)&g_q[(size_t)r0 * LL + n]       = v0;
        *(float2*)&g_q[(size_t)(r0 + 8) * LL + n] = v1;
    }
}

// ---------------------------------------------------------------------------
// Kernel 2: chunk matrix products via bf16 mma (m16n8k16).
// Transposed form: X_s = X_{s-1} * E * diag(q_s), X row-major bf16 in smem.
// E fragments (B side) pinned in registers. Renorm every 8 steps.
// ---------------------------------------------------------------------------
#define SPB 40   // bf16 row stride (80 bytes)

__global__ void __launch_bounds__(32) crf_chunk(const float* __restrict__ trans) {
    __shared__ __nv_bfloat16 Eb[32 * SPB];   // Eb[n][k] = E[k][n]
    __shared__ __nv_bfloat16 Cs[32 * SPB];   // X[m][k] row-major
    __shared__ float qs[CL * 32];

    const int bid = blockIdx.x;
    const int b = bid >> 4, c = bid & 15;
    const int lane = threadIdx.x;
    const int g = lane >> 2, tig = lane & 3;
    const unsigned FULL = 0xffffffffu;

    if (bid == 0 && lane == 0) g_done = 0;   // reset fused-finalize counter

    // stage q rows [c*32, c*32+32)
    {
        const float4* src = (const float4*)(g_q + ((size_t)b * TT + c * CL) * LL);
        float4* dst = (float4*)qs;
#pragma unroll
        for (int i = 0; i < (CL * 32) / (32 * 4); ++i)
            dst[lane + 32 * i] = src[lane + 32 * i];
    }
    // Eb[lane][r] = bf16(exp(trans[r][lane]))  (= E[r][lane])
#pragma unroll
    for (int r = 0; r < 32; ++r)
        Eb[lane * SPB + r] = __float2bfloat16(__expf(trans[r * 32 + lane]));
    __syncwarp();

    // pinned B fragments of E: b0 = {E[k][n], E[k+1][n]}, k = 16kc+2tig, n = 8nt+g
    uint32_t Bf[2][4][2];
#pragma unroll
    for (int kc = 0; kc < 2; ++kc)
#pragma unroll
        for (int nt = 0; nt < 4; ++nt) {
            Bf[kc][nt][0] = *(const uint32_t*)&Eb[(8 * nt + g) * SPB + 16 * kc + 2 * tig];
            Bf[kc][nt][1] = *(const uint32_t*)&Eb[(8 * nt + g) * SPB + 16 * kc + 2 * tig + 8];
        }

    // init X = E * diag(q_{ls0}):  X[m][j] = E[m][j] * q[j]
    const int ls0 = (c == 0) ? 1 : 0;
    {
        const float qj = qs[ls0 * 32 + lane];
#pragma unroll
        for (int m = 0; m < 32; ++m)
            Cs[m * SPB + lane] =
                __float2bfloat16(__bfloat162float(Eb[lane * SPB + m]) * qj);
    }
    __syncwarp();

    float logC = 0.0f;
    for (int ls = ls0 + 1; ls < CL; ++ls) {
        // A fragments from X
        uint32_t Af[2][2][4];
#pragma unroll
        for (int i = 0; i < 2; ++i)
#pragma unroll
            for (int kc = 0; kc < 2; ++kc) {
                const int r0 = (16 * i + g) * SPB + 16 * kc + 2 * tig;
                const int r1 = (16 * i + g + 8) * SPB + 16 * kc + 2 * tig;
                Af[i][kc][0] = *(const uint32_t*)&Cs[r0];
                Af[i][kc][1] = *(const uint32_t*)&Cs[r1];
                Af[i][kc][2] = *(const uint32_t*)&Cs[r0 + 8];
                Af[i][kc][3] = *(const uint32_t*)&Cs[r1 + 8];
            }

        float acc[2][4][4];
#pragma unroll
        for (int i = 0; i < 2; ++i)
#pragma unroll
            for (int nt = 0; nt < 4; ++nt)
#pragma unroll
                for (int v = 0; v < 4; ++v) acc[i][nt][v] = 0.0f;

#pragma unroll
        for (int i = 0; i < 2; ++i)
#pragma unroll
            for (int kc = 0; kc < 2; ++kc)
#pragma unroll
                for (int nt = 0; nt < 4; ++nt)
                    mma_bf16(acc[i][nt],
                             Af[i][kc][0], Af[i][kc][1], Af[i][kc][2], Af[i][kc][3],
                             Bf[kc][nt][0], Bf[kc][nt][1]);

        // column scale by q_ls (cols 8nt+2tig, +1)
#pragma unroll
        for (int nt = 0; nt < 4; ++nt) {
            float2 qv = *(const float2*)&qs[ls * 32 + 8 * nt + 2 * tig];
#pragma unroll
            for (int i = 0; i < 2; ++i) {
                acc[i][nt][0] *= qv.x; acc[i][nt][1] *= qv.y;
                acc[i][nt][2] *= qv.x; acc[i][nt][3] *= qv.y;
            }
        }

        // renorm every 8 steps + final (bf16 exponent = fp32, range is safe)
        if (((ls & 7) == 7) || ls == CL - 1) {
            float m = acc[0][0][0];
#pragma unroll
            for (int i = 0; i < 2; ++i)
#pragma unroll
                for (int nt = 0; nt < 4; ++nt)
#pragma unroll
                    for (int v = 0; v < 4; ++v) m = fmaxf(m, acc[i][nt][v]);
#pragma unroll
            for (int o = 16; o; o >>= 1) m = fmaxf(m, __shfl_xor_sync(FULL, m, o));
            float rinv;
            asm("rcp.approx.f32 %0, %1;" : "=f"(rinv) : "f"(m));
            logC += __logf(m);
#pragma unroll
            for (int i = 0; i < 2; ++i)
#pragma unroll
                for (int nt = 0; nt < 4; ++nt)
#pragma unroll
                    for (int v = 0; v < 4; ++v) acc[i][nt][v] *= rinv;
        }

        // pack (adjacent cols) -> bf16x2, store back
#pragma unroll
        for (int i = 0; i < 2; ++i)
#pragma unroll
            for (int nt = 0; nt < 4; ++nt) {
                uint32_t u01 = bf2pack(acc[i][nt][1], acc[i][nt][0]);
                uint32_t u23 = bf2pack(acc[i][nt][3], acc[i][nt][2]);
                *(uint32_t*)&Cs[(16 * i + g) * SPB + 8 * nt + 2 * tig]     = u01;
                *(uint32_t*)&Cs[(16 * i + g + 8) * SPB + 8 * nt + 2 * tig] = u23;
            }
        __syncwarp();
    }

    // write out: stored[j][i] = C[j][i] = X[i][j]
    float* out = g_cm + (size_t)bid * (LL * LL);
#pragma unroll
    for (int r = 0; r < 32; ++r)
        out[r * 32 + lane] = __bfloat162float(Cs[lane * SPB + r]);
    if (lane == 0) g_cex[bid] = logC;
}

// ---------------------------------------------------------------------------
// Kernel 3: per-sequence combine + fused finalize (last-block pattern).
// Warp 0: p0 -> 16 matvecs; warps 1-3: gold-path numerator.
// ---------------------------------------------------------------------------
#define CMP 33
#define CMB_FLOATS (CH * LL * CMP + LL * LL + TT + 8)
#define CMB_SMEM   (CMB_FLOATS * 4)

__global__ void __launch_bounds__(128) crf_combine(const float* __restrict__ start_t,
                                                   const float* __restrict__ end_t,
                                                   const float* __restrict__ trans,
                                                   const int* __restrict__ labels,
                                                   float* __restrict__ out) {
    extern __shared__ __align__(16) float smf[];
    float* Cm = smf;                              // [CH][32][CMP]
    float* Ts = Cm + CH * LL * CMP;               // [32][32]
    int*   Ls = (int*)(Ts + LL * LL);             // [TT]
    float* res = (float*)(Ls + TT);               // [0]=den, [1..3]=num parts
    __shared__ bool amLast;

    const int b = blockIdx.x;
    const int t = threadIdx.x;
    const int w = t >> 5;
    const int j = t & 31;
    const unsigned FULL = 0xffffffffu;

    {
        const float* src = g_cm + (size_t)b * CH * LL * LL;
        for (int idx = t; idx < CH * LL * LL; idx += 128) {
            int cc = idx >> 10, rem = idx & 1023;
            int r = rem >> 5, col = rem & 31;
            Cm[cc * (LL * CMP) + r * CMP + col] = src[idx];
        }
        ((float4*)Ts)[t]       = ((const float4*)trans)[t];
        ((float4*)Ts)[t + 128] = ((const float4*)trans)[t + 128];
        ((int4*)Ls)[t] = ((const int4*)(labels + b * TT))[t];
    }
    __syncthreads();

    if (w == 0) {
        const float Eend = __expf(end_t[j]);
        float p = __expf(start_t[j]) * g_q[(size_t)b * TT * LL + j];

        float logC = (j < CH) ? g_cex[b * CH + j] : 0.0f;
#pragma unroll
        for (int o = 16; o; o >>= 1) logC += __shfl_xor_sync(FULL, logC, o);

#pragma unroll 1
        for (int c = 0; c < CH; ++c) {
            const float* Cc = Cm + c * (LL * CMP) + j * CMP;
            float s0 = 0.f, s1 = 0.f, s2 = 0.f, s3 = 0.f;
#pragma unroll
            for (int i = 0; i < 32; i += 4) {
                float p0 = __shfl_sync(FULL, p, i + 0);
                float p1 = __shfl_sync(FULL, p, i + 1);
                float p2 = __shfl_sync(FULL, p, i + 2);
                float p3 = __shfl_sync(FULL, p, i + 3);
                s0 = fmaf(p0, Cc[i + 0], s0);
                s1 = fmaf(p1, Cc[i + 1], s1);
                s2 = fmaf(p2, Cc[i + 2], s2);
                s3 = fmaf(p3, Cc[i + 3], s3);
            }
            float pn = (s0 + s1) + (s2 + s3);
            float m = pn;
#pragma unroll
            for (int o = 16; o; o >>= 1) m = fmaxf(m, __shfl_xor_sync(FULL, m, o));
            float rinv;
            asm("rcp.approx.f32 %0, %1;" : "=f"(rinv) : "f"(m));
            logC += __logf(m);
            p = pn * rinv;
        }

        float v = p * Eend;
#pragma unroll
        for (int o = 16; o; o >>= 1) v += __shfl_xor_sync(FULL, v, o);
        if (j == 0) res[0] = logC + __logf(v);
    } else {
        float acc = 0.0f;
        const int gi = (w - 1) * 32 + j;
        for (int tt = 1 + gi; tt < TT; tt += 96) {
            int lp = Ls[tt - 1], lt = Ls[tt];
            acc += Ts[lp * LL + lt] + __logf(g_q[(size_t)b * TT * LL + tt * LL + lt]);
        }
#pragma unroll
        for (int o = 16; o; o >>= 1) acc += __shfl_xor_sync(FULL, acc, o);
        if (j == 0) res[w] = acc;
    }
    __syncthreads();

    if (t == 0) {
        int l0 = Ls[0], lT = Ls[TT - 1];
        float num = res[1] + res[2] + res[3]
                  + start_t[l0] + __logf(g_q[(size_t)b * TT * LL + l0])
                  + end_t[lT];
        g_nll[b] = res[0] - num;
        __threadfence();
        unsigned old = atomicAdd(&g_done, 1u);
        amLast = (old == BB - 1);
    }
    __syncthreads();

    if (amLast && w == 0) {           // fused finalize (deterministic tree)
        __threadfence();
        float v = g_nll[j] + g_nll[j + 32];
#pragma unroll
        for (int o = 16; o; o >>= 1) v += __shfl_xor_sync(FULL, v, o);
        if (j == 0) out[0] = v * (1.0f / (float)BB);
    }
}

// ---------------------------------------------------------------------------
extern "C" void kernel_launch(void* const* d_in, const int* in_sizes, int n_in,
                              void* d_out, int out_size) {
    const float* emb    = (const float*)d_in[0];
    const float* W      = (const float*)d_in[1];
    const float* bias   = (const float*)d_in[2];
    const float* startt = (const float*)d_in[3];
    const float* endt   = (const float*)d_in[4];
    const float* trans  = (const float*)d_in[5];
    const int*   labels = (const int*)d_in[6];

    static int attr_set = 0;
    if (!attr_set) {
        cudaFuncSetAttribute(crf_combine, cudaFuncAttributeMaxDynamicSharedMemorySize,
                             CMB_SMEM);
        attr_set = 1;
    }

    emis_mma<<<(BB * TT) / 64, 128>>>(emb, W, bias);
    crf_chunk<<<BB * CH, 32>>>(trans);
    crf_combine<<<BB, 128, CMB_SMEM>>>(startt, endt, trans, labels, (float*)d_out);
}